// round 1
// baseline (speedup 1.0000x reference)
#include <cuda_runtime.h>
#include <math.h>

#define D        128
#define BM       128
#define BN       128
#define PAD_V    33      // float4 per smem row (132 floats) -> STS.128 conflict-free

__device__ float g_sq[8192];

// ||x_row||^2 per row. One thread per row, vectorized loads.
__global__ void sq_kernel(const float* __restrict__ f, int N) {
    int row = blockIdx.x * blockDim.x + threadIdx.x;
    if (row >= N) return;
    const float4* p = (const float4*)(f + (size_t)row * D);
    float s = 0.f;
#pragma unroll
    for (int i = 0; i < D / 4; i++) {
        float4 v = p[i];
        s = fmaf(v.x, v.x, s);
        s = fmaf(v.y, v.y, s);
        s = fmaf(v.z, v.z, s);
        s = fmaf(v.w, v.w, s);
    }
    g_sq[row] = s;
}

extern __shared__ float4 smem4[];

// 128x128 output tile, full K=128 in smem, 256 threads, 8x8 micro-tile each.
// Thread mapping: m = i*16 + ty, n = j*16 + tx  (strided -> good smem banks + coalesced STG)
__global__ __launch_bounds__(256, 1)
void dist_kernel(const float* __restrict__ f, float* __restrict__ out, int N) {
    float4* As4 = smem4;                 // [BM][PAD_V] float4  (row stride 132 floats)
    float4* Bs4 = smem4 + BM * PAD_V;    // [BN][PAD_V]
    const float* As = (const float*)As4;
    const float* Bs = (const float*)Bs4;

    const int bm  = blockIdx.y * BM;
    const int bn  = blockIdx.x * BN;
    const int tid = threadIdx.x;
    const int tx  = tid & 15;
    const int ty  = tid >> 4;

    // ---- load both 128x128 fp32 tiles (coalesced LDG.128, conflict-free STS.128) ----
#pragma unroll
    for (int it = 0; it < 16; it++) {
        int idx = it * 256 + tid;        // 0..4095 float4 slots
        int r   = idx >> 5;              // 0..127 tile row
        int k4  = idx & 31;              // 0..31 float4 along K
        As4[r * PAD_V + k4] = *(const float4*)(f + (size_t)(bm + r) * D + k4 * 4);
        Bs4[r * PAD_V + k4] = *(const float4*)(f + (size_t)(bn + r) * D + k4 * 4);
    }
    __syncthreads();

    float acc[8][8];
#pragma unroll
    for (int i = 0; i < 8; i++)
#pragma unroll
        for (int j = 0; j < 8; j++) acc[i][j] = 0.f;

    // ---- mainloop: 128 k-steps, 64 FFMA each ----
#pragma unroll 4
    for (int k = 0; k < D; k++) {
        float a[8], b[8];
#pragma unroll
        for (int i = 0; i < 8; i++) a[i] = As[(i * 16 + ty) * (PAD_V * 4) + k];
#pragma unroll
        for (int j = 0; j < 8; j++) b[j] = Bs[(j * 16 + tx) * (PAD_V * 4) + k];
#pragma unroll
        for (int i = 0; i < 8; i++)
#pragma unroll
            for (int j = 0; j < 8; j++)
                acc[i][j] = fmaf(a[i], b[j], acc[i][j]);
    }

    // ---- epilogue: -sqrt(max(sq_i + sq_j - 2*dot, 0)) ----
    float sqa[8], sqb[8];
#pragma unroll
    for (int i = 0; i < 8; i++) sqa[i] = g_sq[bm + i * 16 + ty];
#pragma unroll
    for (int j = 0; j < 8; j++) sqb[j] = g_sq[bn + j * 16 + tx];

#pragma unroll
    for (int i = 0; i < 8; i++) {
        size_t rowoff = (size_t)(bm + i * 16 + ty) * (size_t)N + (size_t)bn;
#pragma unroll
        for (int j = 0; j < 8; j++) {
            float d2 = fmaf(-2.f, acc[i][j], sqa[i] + sqb[j]);
            d2 = fmaxf(d2, 0.f);
            out[rowoff + j * 16 + tx] = -sqrtf(d2);
        }
    }
}

extern "C" void kernel_launch(void* const* d_in, const int* in_sizes, int n_in,
                              void* d_out, int out_size) {
    const float* f   = (const float*)d_in[0];
    float*       out = (float*)d_out;
    const int N = in_sizes[0] / D;   // 8192

    // Row squared-norms (tiny: 4 MB read)
    sq_kernel<<<(N + 255) / 256, 256>>>(f, N);

    // Main tiled kernel with 135 KB dynamic smem (needs opt-in above 48 KB)
    const int smem_bytes = 2 * BM * PAD_V * (int)sizeof(float4);   // 135168
    cudaFuncSetAttribute(dist_kernel,
                         cudaFuncAttributeMaxDynamicSharedMemorySize, smem_bytes);

    dim3 grid(N / BN, N / BM);
    dist_kernel<<<grid, 256, smem_bytes>>>(f, out, N);
}

// round 3
// speedup vs baseline: 3.1437x; 3.1437x over previous
#include <cuda_runtime.h>
#include <cuda_bf16.h>
#include <math.h>
#include <stdint.h>

#define Dk     128
#define NROWS  8192
#define BT     128          // tile dim (BM == BN == 128)

// smem byte offsets (4 operand tiles, 32KB each, then sq slices)
#define SM_AHI   0
#define SM_ALO   (32*1024)
#define SM_BHI   (64*1024)
#define SM_BLO   (96*1024)
#define SM_SQA   (128*1024)
#define SM_SQB   (SM_SQA + 512)
#define SM_TOTAL (SM_SQB + 512)   // 132096 B

__device__ float          g_sq[NROWS];
__device__ __nv_bfloat16  g_hi[NROWS * Dk];
__device__ __nv_bfloat16  g_lo[NROWS * Dk];

__device__ __forceinline__ uint32_t smem_u32(const void* p) {
    uint32_t a;
    asm("{ .reg .u64 t; cvta.to.shared.u64 t, %1; cvt.u32.u64 %0, t; }" : "=r"(a) : "l"(p));
    return a;
}

#define LDSM_X4(r0, r1, r2, r3, addr) \
    asm volatile("ldmatrix.sync.aligned.m8n8.x4.shared.b16 {%0,%1,%2,%3}, [%4];" \
                 : "=r"(r0), "=r"(r1), "=r"(r2), "=r"(r3) : "r"(addr))

#define MMA16816(d, a0, a1, a2, a3, b0, b1) \
    asm volatile("mma.sync.aligned.m16n8k16.row.col.f32.bf16.bf16.f32 " \
                 "{%0,%1,%2,%3}, {%4,%5,%6,%7}, {%8,%9}, {%0,%1,%2,%3};" \
                 : "+f"((d)[0]), "+f"((d)[1]), "+f"((d)[2]), "+f"((d)[3]) \
                 : "r"(a0), "r"(a1), "r"(a2), "r"(a3), "r"(b0), "r"(b1))

// ---------------- precompute kernels ----------------
__global__ void convert_kernel(const float* __restrict__ f) {
    int i = blockIdx.x * blockDim.x + threadIdx.x;   // quad index
    float4 v = ((const float4*)f)[i];
    float x[4] = {v.x, v.y, v.z, v.w};
    __nv_bfloat16 h[4], l[4];
#pragma unroll
    for (int k = 0; k < 4; k++) {
        h[k] = __float2bfloat16_rn(x[k]);
        l[k] = __float2bfloat16_rn(x[k] - __bfloat162float(h[k]));
    }
    *(uint2*)&g_hi[(size_t)i * 4] = *(uint2*)h;
    *(uint2*)&g_lo[(size_t)i * 4] = *(uint2*)l;
}

__global__ void sq_kernel(const float* __restrict__ f, int N) {
    int row = blockIdx.x * blockDim.x + threadIdx.x;
    if (row >= N) return;
    const float4* p = (const float4*)(f + (size_t)row * Dk);
    float s = 0.f;
#pragma unroll
    for (int i = 0; i < Dk / 4; i++) {
        float4 v = p[i];
        s = fmaf(v.x, v.x, s); s = fmaf(v.y, v.y, s);
        s = fmaf(v.z, v.z, s); s = fmaf(v.w, v.w, s);
    }
    g_sq[row] = s;
}

// ---------------- main kernel ----------------
// Upper-triangle tile enumeration: 64*65/2 = 2080 CTAs. Each computes one
// 128x128 tile of dot = hi*hi^T + hi*lo^T + lo*hi^T via mma.sync bf16,
// then stores -sqrt(max(sqi+sqj-2dot,0)) to (I,J) and, if off-diagonal, (J,I).
__global__ __launch_bounds__(256, 1)
void dist_kernel(float* __restrict__ out, int N) {
    extern __shared__ __align__(1024) char smem[];
    const uint32_t sb = smem_u32(smem);

    // ---- tile indices (I <= J) ----
    int idx = blockIdx.x;
    int J = (int)((sqrtf(8.f * idx + 1.f) - 1.f) * 0.5f);
    while ((J + 1) * (J + 2) / 2 <= idx) J++;
    while (J * (J + 1) / 2 > idx) J--;
    int I = idx - J * (J + 1) / 2;
    const int bm = I * BT;           // row block
    const int bn = J * BT;           // col block
    const bool diag = (I == J);

    const int tid = threadIdx.x;
    const int wid = tid >> 5;
    const int l   = tid & 31;

    // ---- load operand tiles: rows of 128 bf16 = 16 x 16B chunks, swizzle c^= (r&7) ----
    const uint4* hi = (const uint4*)g_hi;
    const uint4* lo = (const uint4*)g_lo;
#pragma unroll
    for (int it = 0; it < 8; it++) {
        int u = it * 256 + tid;            // 0..2047
        int r = u >> 4, c = u & 15;
        uint32_t off = r * 256 + (((c ^ (r & 7)) << 4));
        *(uint4*)(smem + SM_AHI + off) = hi[(size_t)(bm + r) * 16 + c];
        *(uint4*)(smem + SM_ALO + off) = lo[(size_t)(bm + r) * 16 + c];
        *(uint4*)(smem + SM_BHI + off) = hi[(size_t)(bn + r) * 16 + c];
        *(uint4*)(smem + SM_BLO + off) = lo[(size_t)(bn + r) * 16 + c];
    }
    if (tid < 128) {
        ((float*)(smem + SM_SQA))[tid] = g_sq[bm + tid];
        ((float*)(smem + SM_SQB))[tid] = g_sq[bn + tid];
    }
    __syncthreads();

    // ---- warp tiling: 4x2 warps, each 32(m) x 64(n) ----
    const int wm = (wid & 3) * 32;
    const int wn = (wid >> 2) * 64;

    // A ldmatrix lane addressing: mt in {0,1}: rows wm+mt*16+ (l&15), chunk = ks*2 + (l>>4)
    uint32_t pA[2], sA[2];
#pragma unroll
    for (int mt = 0; mt < 2; mt++) {
        int r = wm + mt * 16 + (l & 15);
        pA[mt] = r * 256;
        sA[mt] = (r & 7) << 4;
    }
    const int hA = (l >> 4);           // chunk half for A lanes

    // B ldmatrix lane addressing: nt in {0..3}: rows wn+nt*16+((g>>1)<<3)+(l&7), chunk = ks*2+(g&1)
    uint32_t pB[4], sB[4];
    {
        int g = l >> 3;
        int rb = ((g >> 1) << 3) + (l & 7);
#pragma unroll
        for (int nt = 0; nt < 4; nt++) {
            int r = wn + nt * 16 + rb;
            pB[nt] = r * 256;
            sB[nt] = (r & 7) << 4;
        }
    }
    const int hB = ((l >> 3) & 1);     // chunk half for B lanes

    float acc[2][8][4];
#pragma unroll
    for (int mt = 0; mt < 2; mt++)
#pragma unroll
        for (int nt = 0; nt < 8; nt++)
#pragma unroll
            for (int q = 0; q < 4; q++) acc[mt][nt][q] = 0.f;

    // ---- mainloop: 8 k-steps of 16 ----
#pragma unroll
    for (int ks = 0; ks < 8; ks++) {
        uint32_t ahi[2][4], alo[2][4], bhi[4][4], blo[4][4];
        const uint32_t cA = (uint32_t)((ks * 2 + hA) << 4);
        const uint32_t cB = (uint32_t)((ks * 2 + hB) << 4);
#pragma unroll
        for (int mt = 0; mt < 2; mt++) {
            uint32_t offh = pA[mt] + (cA ^ sA[mt]);
            LDSM_X4(ahi[mt][0], ahi[mt][1], ahi[mt][2], ahi[mt][3], sb + SM_AHI + offh);
            LDSM_X4(alo[mt][0], alo[mt][1], alo[mt][2], alo[mt][3], sb + SM_ALO + offh);
        }
#pragma unroll
        for (int nt = 0; nt < 4; nt++) {
            uint32_t offh = pB[nt] + (cB ^ sB[nt]);
            LDSM_X4(bhi[nt][0], bhi[nt][1], bhi[nt][2], bhi[nt][3], sb + SM_BHI + offh);
            LDSM_X4(blo[nt][0], blo[nt][1], blo[nt][2], blo[nt][3], sb + SM_BLO + offh);
        }
        // bhi[nt] regs: {n-tile(2nt): b0,b1, n-tile(2nt+1): b0,b1}
#pragma unroll
        for (int mt = 0; mt < 2; mt++) {
#pragma unroll
            for (int nt = 0; nt < 8; nt++) {
                int n4 = nt >> 1, nh = (nt & 1) * 2;
                MMA16816(acc[mt][nt], ahi[mt][0], ahi[mt][1], ahi[mt][2], ahi[mt][3],
                         bhi[n4][nh], bhi[n4][nh + 1]);
                MMA16816(acc[mt][nt], ahi[mt][0], ahi[mt][1], ahi[mt][2], ahi[mt][3],
                         blo[n4][nh], blo[n4][nh + 1]);
                MMA16816(acc[mt][nt], alo[mt][0], alo[mt][1], alo[mt][2], alo[mt][3],
                         bhi[n4][nh], bhi[n4][nh + 1]);
            }
        }
    }

    // ---- epilogue ----
    const int lr = l >> 2;            // 0..7
    const int lc = (l & 3) * 2;       // 0,2,4,6
    float sqa[2][2], sqb[8][2];
#pragma unroll
    for (int mt = 0; mt < 2; mt++) {
        sqa[mt][0] = ((const float*)(smem + SM_SQA))[wm + mt * 16 + lr];
        sqa[mt][1] = ((const float*)(smem + SM_SQA))[wm + mt * 16 + lr + 8];
    }
#pragma unroll
    for (int nt = 0; nt < 8; nt++) {
        sqb[nt][0] = ((const float*)(smem + SM_SQB))[wn + nt * 8 + lc];
        sqb[nt][1] = ((const float*)(smem + SM_SQB))[wn + nt * 8 + lc + 1];
    }

#pragma unroll
    for (int mt = 0; mt < 2; mt++) {
        const int row0 = bm + wm + mt * 16 + lr;
        const int row1 = row0 + 8;
#pragma unroll
        for (int nt = 0; nt < 8; nt++) {
            const int col = bn + wn + nt * 8 + lc;
            float v00 = -sqrtf(fmaxf(fmaf(-2.f, acc[mt][nt][0], sqa[mt][0] + sqb[nt][0]), 0.f));
            float v01 = -sqrtf(fmaxf(fmaf(-2.f, acc[mt][nt][1], sqa[mt][0] + sqb[nt][1]), 0.f));
            float v10 = -sqrtf(fmaxf(fmaf(-2.f, acc[mt][nt][2], sqa[mt][1] + sqb[nt][0]), 0.f));
            float v11 = -sqrtf(fmaxf(fmaf(-2.f, acc[mt][nt][3], sqa[mt][1] + sqb[nt][1]), 0.f));
            if (diag) {
                if (row0 == col)     v00 = 0.f;
                if (row0 == col + 1) v01 = 0.f;
                if (row1 == col)     v10 = 0.f;
                if (row1 == col + 1) v11 = 0.f;
            }
            // direct orientation (coalesced pairs)
            *(float2*)&out[(size_t)row0 * N + col] = make_float2(v00, v01);
            *(float2*)&out[(size_t)row1 * N + col] = make_float2(v10, v11);
            // transposed orientation (off-diagonal tiles only)
            if (!diag) {
                out[(size_t)col * N + row0]       = v00;
                out[(size_t)col * N + row1]       = v10;
                out[(size_t)(col + 1) * N + row0] = v01;
                out[(size_t)(col + 1) * N + row1] = v11;
            }
        }
    }
}

// ---------------- launch ----------------
extern "C" void kernel_launch(void* const* d_in, const int* in_sizes, int n_in,
                              void* d_out, int out_size) {
    const float* f   = (const float*)d_in[0];
    float*       out = (float*)d_out;
    const int N = in_sizes[0] / Dk;        // 8192
    const int T = N / BT;                  // 64
    const int ntiles = T * (T + 1) / 2;    // 2080

    convert_kernel<<<(N * Dk / 4) / 256, 256>>>(f);
    sq_kernel<<<(N + 255) / 256, 256>>>(f, N);

    cudaFuncSetAttribute(dist_kernel,
                         cudaFuncAttributeMaxDynamicSharedMemorySize, SM_TOTAL);
    dist_kernel<<<ntiles, 256, SM_TOTAL>>>(out, N);
}

// round 6
// speedup vs baseline: 3.3897x; 1.0783x over previous
#include <cuda_runtime.h>
#include <cuda_bf16.h>
#include <math.h>
#include <stdint.h>

#define Dk     128
#define NROWS  8192
#define BM     128
#define BN     64

// smem byte offsets
#define SM_AHI   0
#define SM_ALO   (32*1024)
#define SM_BHI   (64*1024)
#define SM_BLO   (80*1024)
#define SM_SQA   (96*1024)
#define SM_SQB   (SM_SQA + 512)
#define SM_TOTAL (SM_SQB + 256)   // 98560 B -> 2 CTAs/SM

__device__ float          g_sq[NROWS];
__device__ __nv_bfloat16  g_hi[NROWS * Dk];
__device__ __nv_bfloat16  g_lo[NROWS * Dk];

__device__ __forceinline__ uint32_t smem_u32(const void* p) {
    uint32_t a;
    asm("{ .reg .u64 t; cvta.to.shared.u64 t, %1; cvt.u32.u64 %0, t; }" : "=r"(a) : "l"(p));
    return a;
}

#define LDSM_X4(r0, r1, r2, r3, addr) \
    asm volatile("ldmatrix.sync.aligned.m8n8.x4.shared.b16 {%0,%1,%2,%3}, [%4];" \
                 : "=r"(r0), "=r"(r1), "=r"(r2), "=r"(r3) : "r"(addr))

#define MMA16816(d, a0, a1, a2, a3, b0, b1) \
    asm volatile("mma.sync.aligned.m16n8k16.row.col.f32.bf16.bf16.f32 " \
                 "{%0,%1,%2,%3}, {%4,%5,%6,%7}, {%8,%9}, {%0,%1,%2,%3};" \
                 : "+f"((d)[0]), "+f"((d)[1]), "+f"((d)[2]), "+f"((d)[3]) \
                 : "r"(a0), "r"(a1), "r"(a2), "r"(a3), "r"(b0), "r"(b1))

// ---------------- fused precompute: hi/lo split + row squared-norms ----------------
__global__ void prep_kernel(const float* __restrict__ f) {
    const int wid = threadIdx.x >> 5;
    const int l   = threadIdx.x & 31;
    const int row = blockIdx.x * 8 + wid;
    const float4 v = *(const float4*)(f + (size_t)row * Dk + l * 4);
    float x[4] = {v.x, v.y, v.z, v.w};
    __nv_bfloat16 h[4], lo[4];
    float s = 0.f;
#pragma unroll
    for (int k = 0; k < 4; k++) {
        h[k]  = __float2bfloat16_rn(x[k]);
        lo[k] = __float2bfloat16_rn(x[k] - __bfloat162float(h[k]));
        s = fmaf(x[k], x[k], s);
    }
    *(uint2*)&g_hi[(size_t)row * Dk + l * 4] = *(uint2*)h;
    *(uint2*)&g_lo[(size_t)row * Dk + l * 4] = *(uint2*)lo;
#pragma unroll
    for (int d = 16; d > 0; d >>= 1)
        s += __shfl_xor_sync(0xFFFFFFFFu, s, d);
    if (l == 0) g_sq[row] = s;
}

// ---------------- main kernel ----------------
// Tiles (I,J): rows [I*128,I*128+128), cols [J*64,J*64+64), J >= 2I. 4160 CTAs.
// dot = hi*hi^T + hi*lo^T + lo*hi^T via mma.sync bf16; out = -sqrt(max(sqi+sqj-2dot,0)).
// Crossing tiles (J==2I or 2I+1) predicate element ownership.
__global__ __launch_bounds__(256, 2)
void dist_kernel(float* __restrict__ out, int N) {
    extern __shared__ __align__(1024) char smem[];
    const uint32_t sb = smem_u32(smem);

    // ---- tile indices from linear id: off(I) = I*(129-I), integer search ----
    const int idx = blockIdx.x;
    int I = 0;
    while (I < 63 && (I + 1) * (128 - I) <= idx) I++;
    const int J = 2 * I + (idx - I * (129 - I));
    const int bm = I * BM;
    const int bn = J * BN;
    const bool crossing = (J - 2 * I) < 2;

    const int tid = threadIdx.x;
    const int wid = tid >> 5;
    const int l   = tid & 31;

    // ---- load operand tiles: row = 16 x 16B chunks, swizzle c ^= (r&7) ----
    const uint4* hi = (const uint4*)g_hi;
    const uint4* lo = (const uint4*)g_lo;
#pragma unroll
    for (int it = 0; it < 8; it++) {            // A: 128 rows
        int u = it * 256 + tid;
        int r = u >> 4, c = u & 15;
        uint32_t off = r * 256 + ((c ^ (r & 7)) << 4);
        *(uint4*)(smem + SM_AHI + off) = hi[(size_t)(bm + r) * 16 + c];
        *(uint4*)(smem + SM_ALO + off) = lo[(size_t)(bm + r) * 16 + c];
    }
#pragma unroll
    for (int it = 0; it < 4; it++) {            // B: 64 rows
        int u = it * 256 + tid;
        int r = u >> 4, c = u & 15;
        uint32_t off = r * 256 + ((c ^ (r & 7)) << 4);
        *(uint4*)(smem + SM_BHI + off) = hi[(size_t)(bn + r) * 16 + c];
        *(uint4*)(smem + SM_BLO + off) = lo[(size_t)(bn + r) * 16 + c];
    }
    if (tid < 128) ((float*)(smem + SM_SQA))[tid] = g_sq[bm + tid];
    else if (tid < 192) ((float*)(smem + SM_SQB))[tid - 128] = g_sq[bn + tid - 128];
    __syncthreads();

    // ---- warp tiling: 4(m) x 2(n) warps, each 32(m) x 32(n) ----
    const int wm = (wid & 3) * 32;
    const int wn = (wid >> 2) * 32;

    uint32_t pA[2], sA[2];
#pragma unroll
    for (int mt = 0; mt < 2; mt++) {
        int r = wm + mt * 16 + (l & 15);
        pA[mt] = r * 256;
        sA[mt] = (r & 7) << 4;
    }
    const int hA = l >> 4;

    uint32_t pB[2], sB[2];
    {
        int g = l >> 3;
        int rb = ((g >> 1) << 3) + (l & 7);
#pragma unroll
        for (int nt = 0; nt < 2; nt++) {
            int r = wn + nt * 16 + rb;
            pB[nt] = r * 256;
            sB[nt] = (r & 7) << 4;
        }
    }
    const int hB = (l >> 3) & 1;

    float acc[2][4][4];
#pragma unroll
    for (int mt = 0; mt < 2; mt++)
#pragma unroll
        for (int nt = 0; nt < 4; nt++)
#pragma unroll
            for (int q = 0; q < 4; q++) acc[mt][nt][q] = 0.f;

    // ---- mainloop: 8 k-steps of 16 ----
#pragma unroll
    for (int ks = 0; ks < 8; ks++) {
        uint32_t ahi[2][4], alo[2][4], bhi[2][4], blo[2][4];
        const uint32_t cA = (uint32_t)((ks * 2 + hA) << 4);
        const uint32_t cB = (uint32_t)((ks * 2 + hB) << 4);
#pragma unroll
        for (int mt = 0; mt < 2; mt++) {
            uint32_t o = pA[mt] + (cA ^ sA[mt]);
            LDSM_X4(ahi[mt][0], ahi[mt][1], ahi[mt][2], ahi[mt][3], sb + SM_AHI + o);
            LDSM_X4(alo[mt][0], alo[mt][1], alo[mt][2], alo[mt][3], sb + SM_ALO + o);
        }
#pragma unroll
        for (int nt = 0; nt < 2; nt++) {
            uint32_t o = pB[nt] + (cB ^ sB[nt]);
            LDSM_X4(bhi[nt][0], bhi[nt][1], bhi[nt][2], bhi[nt][3], sb + SM_BHI + o);
            LDSM_X4(blo[nt][0], blo[nt][1], blo[nt][2], blo[nt][3], sb + SM_BLO + o);
        }
#pragma unroll
        for (int mt = 0; mt < 2; mt++) {
#pragma unroll
            for (int n8 = 0; n8 < 4; n8++) {
                int n4 = n8 >> 1, nh = (n8 & 1) * 2;
                MMA16816(acc[mt][n8], ahi[mt][0], ahi[mt][1], ahi[mt][2], ahi[mt][3],
                         bhi[n4][nh], bhi[n4][nh + 1]);
                MMA16816(acc[mt][n8], ahi[mt][0], ahi[mt][1], ahi[mt][2], ahi[mt][3],
                         blo[n4][nh], blo[n4][nh + 1]);
                MMA16816(acc[mt][n8], alo[mt][0], alo[mt][1], alo[mt][2], alo[mt][3],
                         bhi[n4][nh], bhi[n4][nh + 1]);
            }
        }
    }

    // ---- epilogue ----
    const int lr = l >> 2;            // 0..7
    const int lc = (l & 3) * 2;       // 0,2,4,6
    float sqa[2][2], sqb[4][2];
#pragma unroll
    for (int mt = 0; mt < 2; mt++) {
        sqa[mt][0] = ((const float*)(smem + SM_SQA))[wm + mt * 16 + lr];
        sqa[mt][1] = ((const float*)(smem + SM_SQA))[wm + mt * 16 + lr + 8];
    }
#pragma unroll
    for (int nt = 0; nt < 4; nt++) {
        sqb[nt][0] = ((const float*)(smem + SM_SQB))[wn + nt * 8 + lc];
        sqb[nt][1] = ((const float*)(smem + SM_SQB))[wn + nt * 8 + lc + 1];
    }

#pragma unroll
    for (int mt = 0; mt < 2; mt++) {
        const int row0 = bm + wm + mt * 16 + lr;
        const int row1 = row0 + 8;
#pragma unroll
        for (int nt = 0; nt < 4; nt++) {
            const int col = bn + wn + nt * 8 + lc;
            float v00 = -sqrtf(fmaxf(fmaf(-2.f, acc[mt][nt][0], sqa[mt][0] + sqb[nt][0]), 0.f));
            float v01 = -sqrtf(fmaxf(fmaf(-2.f, acc[mt][nt][1], sqa[mt][0] + sqb[nt][1]), 0.f));
            float v10 = -sqrtf(fmaxf(fmaf(-2.f, acc[mt][nt][2], sqa[mt][1] + sqb[nt][0]), 0.f));
            float v11 = -sqrtf(fmaxf(fmaf(-2.f, acc[mt][nt][3], sqa[mt][1] + sqb[nt][1]), 0.f));
            if (!crossing) {
                *(float2*)&out[(size_t)row0 * N + col] = make_float2(v00, v01);
                *(float2*)&out[(size_t)row1 * N + col] = make_float2(v10, v11);
                out[(size_t)col * N + row0]       = v00;
                out[(size_t)col * N + row1]       = v10;
                out[(size_t)(col + 1) * N + row0] = v01;
                out[(size_t)(col + 1) * N + row1] = v11;
            } else {
                // element-wise ownership: col>row -> both; col==row -> 0; col<row -> skip
                if (col > row0) {
                    out[(size_t)row0 * N + col] = v00;
                    out[(size_t)col * N + row0] = v00;
                } else if (col == row0) out[(size_t)row0 * N + col] = 0.f;
                if (col + 1 > row0) {
                    out[(size_t)row0 * N + col + 1] = v01;
                    out[(size_t)(col + 1) * N + row0] = v01;
                } else if (col + 1 == row0) out[(size_t)row0 * N + col + 1] = 0.f;
                if (col > row1) {
                    out[(size_t)row1 * N + col] = v10;
                    out[(size_t)col * N + row1] = v10;
                } else if (col == row1) out[(size_t)row1 * N + col] = 0.f;
                if (col + 1 > row1) {
                    out[(size_t)row1 * N + col + 1] = v11;
                    out[(size_t)(col + 1) * N + row1] = v11;
                } else if (col + 1 == row1) out[(size_t)row1 * N + col + 1] = 0.f;
            }
        }
    }
}

// ---------------- launch ----------------
extern "C" void kernel_launch(void* const* d_in, const int* in_sizes, int n_in,
                              void* d_out, int out_size) {
    const float* f   = (const float*)d_in[0];
    float*       out = (float*)d_out;
    const int N = in_sizes[0] / Dk;        // 8192

    prep_kernel<<<N / 8, 256>>>(f);

    cudaFuncSetAttribute(dist_kernel,
                         cudaFuncAttributeMaxDynamicSharedMemorySize, SM_TOTAL);
    const int ntiles = 4160;               // sum_{I=0}^{63} (128 - 2I)
    dist_kernel<<<ntiles, 256, SM_TOTAL>>>(out, N);
}

// round 8
// speedup vs baseline: 4.6858x; 1.3824x over previous
#include <cuda_runtime.h>
#include <cuda_bf16.h>
#include <math.h>
#include <stdint.h>

#define Dk     128
#define NROWS  8192
#define BT     128          // square tile

// smem byte offsets
#define SM_AHI   0
#define SM_BHI   (32*1024)
#define SM_BLO   (64*1024)
#define SM_SQA   (96*1024)
#define SM_SQB   (SM_SQA + 512)
#define SM_TOTAL (SM_SQB + 512)   // 99328 B -> 2 CTAs/SM

__device__ float          g_sq[NROWS];
__device__ __nv_bfloat16  g_hi[NROWS * Dk];
__device__ __nv_bfloat16  g_lo[NROWS * Dk];

__device__ __forceinline__ uint32_t smem_u32(const void* p) {
    uint32_t a;
    asm("{ .reg .u64 t; cvta.to.shared.u64 t, %1; cvt.u32.u64 %0, t; }" : "=r"(a) : "l"(p));
    return a;
}

#define LDSM_X4(r0, r1, r2, r3, addr) \
    asm volatile("ldmatrix.sync.aligned.m8n8.x4.shared.b16 {%0,%1,%2,%3}, [%4];" \
                 : "=r"(r0), "=r"(r1), "=r"(r2), "=r"(r3) : "r"(addr))

#define MMA16816(d, a0, a1, a2, a3, b0, b1) \
    asm volatile("mma.sync.aligned.m16n8k16.row.col.f32.bf16.bf16.f32 " \
                 "{%0,%1,%2,%3}, {%4,%5,%6,%7}, {%8,%9}, {%0,%1,%2,%3};" \
                 : "+f"((d)[0]), "+f"((d)[1]), "+f"((d)[2]), "+f"((d)[3]) \
                 : "r"(a0), "r"(a1), "r"(a2), "r"(a3), "r"(b0), "r"(b1))

// ---------------- fused precompute: hi/lo split + row squared-norms ----------------
__global__ void prep_kernel(const float* __restrict__ f) {
    const int wid = threadIdx.x >> 5;
    const int l   = threadIdx.x & 31;
    const int row = blockIdx.x * 8 + wid;
    const float4 v = *(const float4*)(f + (size_t)row * Dk + l * 4);
    float x[4] = {v.x, v.y, v.z, v.w};
    __nv_bfloat16 h[4], lo[4];
    float s = 0.f;
#pragma unroll
    for (int k = 0; k < 4; k++) {
        h[k]  = __float2bfloat16_rn(x[k]);
        lo[k] = __float2bfloat16_rn(x[k] - __bfloat162float(h[k]));
        s = fmaf(x[k], x[k], s);
    }
    *(uint2*)&g_hi[(size_t)row * Dk + l * 4] = *(uint2*)h;
    *(uint2*)&g_lo[(size_t)row * Dk + l * 4] = *(uint2*)lo;
#pragma unroll
    for (int d = 16; d > 0; d >>= 1)
        s += __shfl_xor_sync(0xFFFFFFFFu, s, d);
    if (l == 0) g_sq[row] = s;
}

// ---------------- main kernel ----------------
// Upper-triangle square tiles (I<=J): 2080 CTAs. dot = Ahi*(Bhi+Blo)^T (2-term split).
// out = -sqrt(max(sqi+sqj-2dot,0)); each off-diag tile stored to (I,J) and (J,I).
__global__ __launch_bounds__(256, 2)
void dist_kernel(float* __restrict__ out, int N) {
    extern __shared__ __align__(1024) char smem[];
    const uint32_t sb = smem_u32(smem);

    // ---- tile indices (I <= J) ----
    const int idx = blockIdx.x;
    int J = (int)((sqrtf(8.f * idx + 1.f) - 1.f) * 0.5f);
    while ((J + 1) * (J + 2) / 2 <= idx) J++;
    while (J * (J + 1) / 2 > idx) J--;
    const int I = idx - J * (J + 1) / 2;
    const int bm = I * BT;
    const int bn = J * BT;
    const bool diag = (I == J);

    const int tid = threadIdx.x;
    const int wid = tid >> 5;
    const int l   = tid & 31;

    // ---- load operand tiles: row = 16 x 16B chunks, swizzle c ^= (r&7) ----
    const uint4* hi = (const uint4*)g_hi;
    const uint4* lo = (const uint4*)g_lo;
#pragma unroll
    for (int it = 0; it < 8; it++) {
        int u = it * 256 + tid;            // 0..2047
        int r = u >> 4, c = u & 15;
        uint32_t off = r * 256 + ((c ^ (r & 7)) << 4);
        *(uint4*)(smem + SM_AHI + off) = hi[(size_t)(bm + r) * 16 + c];
        *(uint4*)(smem + SM_BHI + off) = hi[(size_t)(bn + r) * 16 + c];
        *(uint4*)(smem + SM_BLO + off) = lo[(size_t)(bn + r) * 16 + c];
    }
    if (tid < 128) ((float*)(smem + SM_SQA))[tid] = g_sq[bm + tid];
    else ((float*)(smem + SM_SQB))[tid - 128] = g_sq[bn + tid - 128];
    __syncthreads();

    // ---- warp tiling: 4(m) x 2(n) warps, each 32(m) x 64(n) ----
    const int wm = (wid & 3) * 32;
    const int wn = (wid >> 2) * 64;

    uint32_t pA[2], sA[2];
#pragma unroll
    for (int mt = 0; mt < 2; mt++) {
        int r = wm + mt * 16 + (l & 15);
        pA[mt] = r * 256;
        sA[mt] = (r & 7) << 4;
    }
    const int hA = l >> 4;

    uint32_t pB[4], sB[4];
    {
        int g = l >> 3;
        int rb = ((g >> 1) << 3) + (l & 7);
#pragma unroll
        for (int nt = 0; nt < 4; nt++) {
            int r = wn + nt * 16 + rb;
            pB[nt] = r * 256;
            sB[nt] = (r & 7) << 4;
        }
    }
    const int hB = (l >> 3) & 1;

    float acc[2][8][4];
#pragma unroll
    for (int mt = 0; mt < 2; mt++)
#pragma unroll
        for (int nt = 0; nt < 8; nt++)
#pragma unroll
            for (int q = 0; q < 4; q++) acc[mt][nt][q] = 0.f;

    // ---- mainloop: 8 k-steps of 16; 2 terms: Ahi*Bhi + Ahi*Blo ----
#pragma unroll
    for (int ks = 0; ks < 8; ks++) {
        const uint32_t cA = (uint32_t)((ks * 2 + hA) << 4);
        const uint32_t cB = (uint32_t)((ks * 2 + hB) << 4);
        uint32_t ahi[2][4];
#pragma unroll
        for (int mt = 0; mt < 2; mt++) {
            uint32_t o = pA[mt] + (cA ^ sA[mt]);
            LDSM_X4(ahi[mt][0], ahi[mt][1], ahi[mt][2], ahi[mt][3], sb + SM_AHI + o);
        }
#pragma unroll
        for (int n4 = 0; n4 < 4; n4++) {
            uint32_t o = pB[n4] + (cB ^ sB[n4]);
            uint32_t bh[4], bl[4];
            LDSM_X4(bh[0], bh[1], bh[2], bh[3], sb + SM_BHI + o);
            LDSM_X4(bl[0], bl[1], bl[2], bl[3], sb + SM_BLO + o);
#pragma unroll
            for (int mt = 0; mt < 2; mt++) {
#pragma unroll
                for (int nh = 0; nh < 2; nh++) {
                    MMA16816(acc[mt][n4 * 2 + nh], ahi[mt][0], ahi[mt][1], ahi[mt][2], ahi[mt][3],
                             bh[nh * 2], bh[nh * 2 + 1]);
                    MMA16816(acc[mt][n4 * 2 + nh], ahi[mt][0], ahi[mt][1], ahi[mt][2], ahi[mt][3],
                             bl[nh * 2], bl[nh * 2 + 1]);
                }
            }
        }
    }

    // ---- epilogue ----
    const int lr = l >> 2;            // 0..7
    const int lc = (l & 3) * 2;       // 0,2,4,6
    float sqa[2][2], sqb[8][2];
#pragma unroll
    for (int mt = 0; mt < 2; mt++) {
        sqa[mt][0] = ((const float*)(smem + SM_SQA))[wm + mt * 16 + lr];
        sqa[mt][1] = ((const float*)(smem + SM_SQA))[wm + mt * 16 + lr + 8];
    }
#pragma unroll
    for (int nt = 0; nt < 8; nt++) {
        sqb[nt][0] = ((const float*)(smem + SM_SQB))[wn + nt * 8 + lc];
        sqb[nt][1] = ((const float*)(smem + SM_SQB))[wn + nt * 8 + lc + 1];
    }

#pragma unroll
    for (int mt = 0; mt < 2; mt++) {
        const int row0 = bm + wm + mt * 16 + lr;
        const int row1 = row0 + 8;
#pragma unroll
        for (int nt = 0; nt < 8; nt++) {
            const int col = bn + wn + nt * 8 + lc;
            float v00 = -sqrtf(fmaxf(fmaf(-2.f, acc[mt][nt][0], sqa[mt][0] + sqb[nt][0]), 0.f));
            float v01 = -sqrtf(fmaxf(fmaf(-2.f, acc[mt][nt][1], sqa[mt][0] + sqb[nt][1]), 0.f));
            float v10 = -sqrtf(fmaxf(fmaf(-2.f, acc[mt][nt][2], sqa[mt][1] + sqb[nt][0]), 0.f));
            float v11 = -sqrtf(fmaxf(fmaf(-2.f, acc[mt][nt][3], sqa[mt][1] + sqb[nt][1]), 0.f));
            if (!diag) {
                *(float2*)&out[(size_t)row0 * N + col] = make_float2(v00, v01);
                *(float2*)&out[(size_t)row1 * N + col] = make_float2(v10, v11);
                out[(size_t)col * N + row0]       = v00;
                out[(size_t)col * N + row1]       = v10;
                out[(size_t)(col + 1) * N + row0] = v01;
                out[(size_t)(col + 1) * N + row1] = v11;
            } else {
                // element-wise ownership: col>row -> both; col==row -> 0; col<row -> skip
                if (col > row0) {
                    out[(size_t)row0 * N + col] = v00;
                    out[(size_t)col * N + row0] = v00;
                } else if (col == row0) out[(size_t)row0 * N + col] = 0.f;
                if (col + 1 > row0) {
                    out[(size_t)row0 * N + col + 1] = v01;
                    out[(size_t)(col + 1) * N + row0] = v01;
                } else if (col + 1 == row0) out[(size_t)row0 * N + col + 1] = 0.f;
                if (col > row1) {
                    out[(size_t)row1 * N + col] = v10;
                    out[(size_t)col * N + row1] = v10;
                } else if (col == row1) out[(size_t)row1 * N + col] = 0.f;
                if (col + 1 > row1) {
                    out[(size_t)row1 * N + col + 1] = v11;
                    out[(size_t)(col + 1) * N + row1] = v11;
                } else if (col + 1 == row1) out[(size_t)row1 * N + col + 1] = 0.f;
            }
        }
    }
}

// ---------------- launch ----------------
extern "C" void kernel_launch(void* const* d_in, const int* in_sizes, int n_in,
                              void* d_out, int out_size) {
    const float* f   = (const float*)d_in[0];
    float*       out = (float*)d_out;
    const int N = in_sizes[0] / Dk;        // 8192
    const int T = N / BT;                  // 64
    const int ntiles = T * (T + 1) / 2;    // 2080

    prep_kernel<<<N / 8, 256>>>(f);

    cudaFuncSetAttribute(dist_kernel,
                         cudaFuncAttributeMaxDynamicSharedMemorySize, SM_TOTAL);
    dist_kernel<<<ntiles, 256, SM_TOTAL>>>(out, N);
}

// round 9
// speedup vs baseline: 5.9932x; 1.2790x over previous
#include <cuda_runtime.h>
#include <cuda_fp16.h>
#include <math.h>
#include <stdint.h>

#define Dk     128
#define NROWS  8192
#define BT     128          // square tile

// smem byte offsets
#define SM_A     0
#define SM_B     (32*1024)
#define SM_SQA   (64*1024)
#define SM_SQB   (SM_SQA + 512)
#define SM_TOTAL (SM_SQB + 512)   // 66560 B

__device__ float   g_sq[NROWS];
__device__ __half  g_h[NROWS * Dk];

__device__ __forceinline__ uint32_t smem_u32(const void* p) {
    uint32_t a;
    asm("{ .reg .u64 t; cvta.to.shared.u64 t, %1; cvt.u32.u64 %0, t; }" : "=r"(a) : "l"(p));
    return a;
}

#define LDSM_X4(r0, r1, r2, r3, addr) \
    asm volatile("ldmatrix.sync.aligned.m8n8.x4.shared.b16 {%0,%1,%2,%3}, [%4];" \
                 : "=r"(r0), "=r"(r1), "=r"(r2), "=r"(r3) : "r"(addr))

#define MMA16816F16(d, a0, a1, a2, a3, b0, b1) \
    asm volatile("mma.sync.aligned.m16n8k16.row.col.f32.f16.f16.f32 " \
                 "{%0,%1,%2,%3}, {%4,%5,%6,%7}, {%8,%9}, {%0,%1,%2,%3};" \
                 : "+f"((d)[0]), "+f"((d)[1]), "+f"((d)[2]), "+f"((d)[3]) \
                 : "r"(a0), "r"(a1), "r"(a2), "r"(a3), "r"(b0), "r"(b1))

// ---------------- fused precompute: fp16 convert + row squared-norms ----------------
__global__ void prep_kernel(const float* __restrict__ f) {
    const int wid = threadIdx.x >> 5;
    const int l   = threadIdx.x & 31;
    const int row = blockIdx.x * 8 + wid;
    const float4 v = *(const float4*)(f + (size_t)row * Dk + l * 4);
    float x[4] = {v.x, v.y, v.z, v.w};
    __half h[4];
    float s = 0.f;
#pragma unroll
    for (int k = 0; k < 4; k++) {
        h[k] = __float2half_rn(x[k]);
        s = fmaf(x[k], x[k], s);
    }
    *(uint2*)&g_h[(size_t)row * Dk + l * 4] = *(uint2*)h;
#pragma unroll
    for (int d = 16; d > 0; d >>= 1)
        s += __shfl_xor_sync(0xFFFFFFFFu, s, d);
    if (l == 0) g_sq[row] = s;
}

// ---------------- main kernel ----------------
// Upper-triangle square tiles (I<=J): 2080 CTAs. dot = fp16(A)*fp16(B)^T, f32 accum.
// out = -sqrt(max(sqi+sqj-2dot,0)); off-diag tiles stored to (I,J) and (J,I).
__global__ __launch_bounds__(256, 2)
void dist_kernel(float* __restrict__ out, int N) {
    extern __shared__ __align__(1024) char smem[];
    const uint32_t sb = smem_u32(smem);

    // ---- tile indices (I <= J) ----
    const int idx = blockIdx.x;
    int J = (int)((sqrtf(8.f * idx + 1.f) - 1.f) * 0.5f);
    while ((J + 1) * (J + 2) / 2 <= idx) J++;
    while (J * (J + 1) / 2 > idx) J--;
    const int I = idx - J * (J + 1) / 2;
    const int bm = I * BT;
    const int bn = J * BT;
    const bool diag = (I == J);

    const int tid = threadIdx.x;
    const int wid = tid >> 5;
    const int l   = tid & 31;

    // ---- load operand tiles: row = 16 x 16B chunks, swizzle c ^= (r&7) ----
    const uint4* h = (const uint4*)g_h;
#pragma unroll
    for (int it = 0; it < 8; it++) {
        int u = it * 256 + tid;            // 0..2047
        int r = u >> 4, c = u & 15;
        uint32_t off = r * 256 + ((c ^ (r & 7)) << 4);
        *(uint4*)(smem + SM_A + off) = h[(size_t)(bm + r) * 16 + c];
        *(uint4*)(smem + SM_B + off) = h[(size_t)(bn + r) * 16 + c];
    }
    if (tid < 128) ((float*)(smem + SM_SQA))[tid] = g_sq[bm + tid];
    else ((float*)(smem + SM_SQB))[tid - 128] = g_sq[bn + tid - 128];
    __syncthreads();

    // ---- warp tiling: 4(m) x 2(n) warps, each 32(m) x 64(n) ----
    const int wm = (wid & 3) * 32;
    const int wn = (wid >> 2) * 64;

    uint32_t pA[2], sA[2];
#pragma unroll
    for (int mt = 0; mt < 2; mt++) {
        int r = wm + mt * 16 + (l & 15);
        pA[mt] = r * 256;
        sA[mt] = (r & 7) << 4;
    }
    const int hA = l >> 4;

    uint32_t pB[4], sB[4];
    {
        int g = l >> 3;
        int rb = ((g >> 1) << 3) + (l & 7);
#pragma unroll
        for (int nt = 0; nt < 4; nt++) {
            int r = wn + nt * 16 + rb;
            pB[nt] = r * 256;
            sB[nt] = (r & 7) << 4;
        }
    }
    const int hB = (l >> 3) & 1;

    float acc[2][8][4];
#pragma unroll
    for (int mt = 0; mt < 2; mt++)
#pragma unroll
        for (int nt = 0; nt < 8; nt++)
#pragma unroll
            for (int q = 0; q < 4; q++) acc[mt][nt][q] = 0.f;

    // ---- mainloop: 8 k-steps of 16, single fp16 term ----
#pragma unroll
    for (int ks = 0; ks < 8; ks++) {
        const uint32_t cA = (uint32_t)((ks * 2 + hA) << 4);
        const uint32_t cB = (uint32_t)((ks * 2 + hB) << 4);
        uint32_t a[2][4];
#pragma unroll
        for (int mt = 0; mt < 2; mt++) {
            uint32_t o = pA[mt] + (cA ^ sA[mt]);
            LDSM_X4(a[mt][0], a[mt][1], a[mt][2], a[mt][3], sb + SM_A + o);
        }
#pragma unroll
        for (int n4 = 0; n4 < 4; n4++) {
            uint32_t o = pB[n4] + (cB ^ sB[n4]);
            uint32_t b[4];
            LDSM_X4(b[0], b[1], b[2], b[3], sb + SM_B + o);
#pragma unroll
            for (int mt = 0; mt < 2; mt++) {
#pragma unroll
                for (int nh = 0; nh < 2; nh++) {
                    MMA16816F16(acc[mt][n4 * 2 + nh], a[mt][0], a[mt][1], a[mt][2], a[mt][3],
                                b[nh * 2], b[nh * 2 + 1]);
                }
            }
        }
    }

    // ---- epilogue ----
    const int lr = l >> 2;            // 0..7
    const int lc = (l & 3) * 2;       // 0,2,4,6
    float sqa[2][2], sqb[8][2];
#pragma unroll
    for (int mt = 0; mt < 2; mt++) {
        sqa[mt][0] = ((const float*)(smem + SM_SQA))[wm + mt * 16 + lr];
        sqa[mt][1] = ((const float*)(smem + SM_SQA))[wm + mt * 16 + lr + 8];
    }
#pragma unroll
    for (int nt = 0; nt < 8; nt++) {
        sqb[nt][0] = ((const float*)(smem + SM_SQB))[wn + nt * 8 + lc];
        sqb[nt][1] = ((const float*)(smem + SM_SQB))[wn + nt * 8 + lc + 1];
    }

#pragma unroll
    for (int mt = 0; mt < 2; mt++) {
        const int row0 = bm + wm + mt * 16 + lr;
        const int row1 = row0 + 8;
#pragma unroll
        for (int nt = 0; nt < 8; nt++) {
            const int col = bn + wn + nt * 8 + lc;
            float v00 = -sqrtf(fmaxf(fmaf(-2.f, acc[mt][nt][0], sqa[mt][0] + sqb[nt][0]), 0.f));
            float v01 = -sqrtf(fmaxf(fmaf(-2.f, acc[mt][nt][1], sqa[mt][0] + sqb[nt][1]), 0.f));
            float v10 = -sqrtf(fmaxf(fmaf(-2.f, acc[mt][nt][2], sqa[mt][1] + sqb[nt][0]), 0.f));
            float v11 = -sqrtf(fmaxf(fmaf(-2.f, acc[mt][nt][3], sqa[mt][1] + sqb[nt][1]), 0.f));
            if (!diag) {
                *(float2*)&out[(size_t)row0 * N + col] = make_float2(v00, v01);
                *(float2*)&out[(size_t)row1 * N + col] = make_float2(v10, v11);
                out[(size_t)col * N + row0]       = v00;
                out[(size_t)col * N + row1]       = v10;
                out[(size_t)(col + 1) * N + row0] = v01;
                out[(size_t)(col + 1) * N + row1] = v11;
            } else {
                // element-wise ownership: col>row -> both; col==row -> 0; col<row -> skip
                if (col > row0) {
                    out[(size_t)row0 * N + col] = v00;
                    out[(size_t)col * N + row0] = v00;
                } else if (col == row0) out[(size_t)row0 * N + col] = 0.f;
                if (col + 1 > row0) {
                    out[(size_t)row0 * N + col + 1] = v01;
                    out[(size_t)(col + 1) * N + row0] = v01;
                } else if (col + 1 == row0) out[(size_t)row0 * N + col + 1] = 0.f;
                if (col > row1) {
                    out[(size_t)row1 * N + col] = v10;
                    out[(size_t)col * N + row1] = v10;
                } else if (col == row1) out[(size_t)row1 * N + col] = 0.f;
                if (col + 1 > row1) {
                    out[(size_t)row1 * N + col + 1] = v11;
                    out[(size_t)(col + 1) * N + row1] = v11;
                } else if (col + 1 == row1) out[(size_t)row1 * N + col + 1] = 0.f;
            }
        }
    }
}

// ---------------- launch ----------------
extern "C" void kernel_launch(void* const* d_in, const int* in_sizes, int n_in,
                              void* d_out, int out_size) {
    const float* f   = (const float*)d_in[0];
    float*       out = (float*)d_out;
    const int N = in_sizes[0] / Dk;        // 8192
    const int T = N / BT;                  // 64
    const int ntiles = T * (T + 1) / 2;    // 2080

    prep_kernel<<<N / 8, 256>>>(f);

    cudaFuncSetAttribute(dist_kernel,
                         cudaFuncAttributeMaxDynamicSharedMemorySize, SM_TOTAL);
    dist_kernel<<<ntiles, 256, SM_TOTAL>>>(out, N);
}